// round 15
// baseline (speedup 1.0000x reference)
#include <cuda_runtime.h>
#include <cuda_bf16.h>
#include <cstdint>

#define CH    512
#define FH    64
#define FW    96
#define HW    6144          // 64*96
#define KDIM  4608          // 512*9
#define KHALF 2304          // 256 channels * 9
#define CHALF 256
#define NANCH 55296         // HW*9
#define NSORT 65536
#define PRE_NMS  6000
#define POST_NMS 300

typedef unsigned long long u64;
typedef unsigned int u32;

// ------------- device scratch (no allocation allowed) -------------
__device__ float g_xa[CH * HW];       // conv partial, K-half 0 (raw)
__device__ float g_xb[CH * HW];       // conv partial, K-half 1
__device__ float4 g_boxes[NANCH];
__device__ u64   g_keys[NSORT];

// base anchors, exact per reference _base_anchors() (verified passing r9)
__constant__ float c_anch[36] = {
    -84.f,  -40.f,  99.f,  55.f,
   -176.f,  -88.f, 191.f, 103.f,
   -360.f, -184.f, 375.f, 199.f,
    -56.f,  -56.f,  71.f,  71.f,
   -120.f, -120.f, 135.f, 135.f,
   -248.f, -248.f, 263.f, 263.f,
    -36.f,  -80.f,  51.f,  95.f,
    -80.f, -168.f,  95.f, 183.f,
   -168.f, -344.f, 183.f, 359.f
};

// ------------- packed fp32x2 helpers -------------
__device__ __forceinline__ u64 ffma2(u64 a, u64 b, u64 c) {
    u64 d;
    asm("fma.rn.f32x2 %0, %1, %2, %3;" : "=l"(d) : "l"(a), "l"(b), "l"(c));
    return d;
}
__device__ __forceinline__ u64 dup2(float v) {
    u32 u = __float_as_uint(v);
    return ((u64)u << 32) | (u64)u;
}

// =====================================================================
// Kernel 1: 3x3 conv 512->512, implicit GEMM, K split x2 (gridDim.z).
// Tile 64M x 128N, BK=16, 128 threads, micro 8M x 8N via FFMA2.
// r15: A DUPLICATED in smem (store-side dup -> zero-MOV pair reads),
//      B swizzled (r14), DOUBLE-BUFFERED smem (1 barrier/tile),
//      next-tile global loads issued before compute (latency hidden).
// Same FFMA2 lane math in the same order as the passing r13/r14.
// =====================================================================
__global__ void __launch_bounds__(128) conv3_kernel(
        const float* __restrict__ feat,   // [512][64][96]
        const float* __restrict__ w) {    // [512][4608]
    __shared__ __align__(16) float As2[2][16][128];  // [buf][k][2*m] dup pairs
    __shared__ __align__(16) float Bs [2][16][128];  // [buf][k][swizzled n]

    const int tid = threadIdx.x;
    const int n0  = blockIdx.x * 128;
    const int co0 = blockIdx.y * 64;
    const int half = blockIdx.z;          // 0 or 1
    const int kbase = half * KHALF;
    const int cibase = half * CHALF;
    float* gout = half ? g_xb : g_xa;

    const int tng = tid & 15;     // 16 N-groups of 8
    const int tmg = tid >> 4;     // 8  M-groups of 8
    const int sel = (tng >> 2) & 1;
    const int boff0 = tng * 8 + 4 * sel;        // physical idx of logical N 0-3
    const int boff1 = tng * 8 + 4 - 4 * sel;    // physical idx of logical N 4-7

    const int a_m  = tid >> 1;
    const int a_kq = (tid & 1) * 8;
    const float* a_src = w + (size_t)(co0 + a_m) * KDIM + kbase;

    const int nn   = tid;
    const int nnp  = nn ^ (((nn >> 5) & 1) << 2);   // swizzled store column
    const int n    = n0 + nn;
    const int ph   = n / FW;
    const int pw   = n - ph * FW;
    int ci = cibase, r = 0;       // sequential k walk for gathers

    const int NIT = KHALF / 16;   // 144

    u64 acc[8][4];
#pragma unroll
    for (int i = 0; i < 8; i++)
#pragma unroll
        for (int p = 0; p < 4; p++) acc[i][p] = 0ull;

    float4 v0, v1;
    float bvals[16];

    // ---- gather one 16-k B slab for this thread's pixel (advances ci,r)
#define GATHER_B()                                                        \
    do {                                                                  \
        _Pragma("unroll")                                                 \
        for (int q = 0; q < 16; q++) {                                    \
            int rq = r;                                                   \
            int dh = rq / 3 - 1;                                          \
            int dw = rq - (rq / 3) * 3 - 1;                               \
            int hh = ph + dh, ww = pw + dw;                               \
            float val = 0.f;                                              \
            if ((unsigned)hh < (unsigned)FH && (unsigned)ww < (unsigned)FW) \
                val = feat[ci * HW + hh * FW + ww];                       \
            bvals[q] = val;                                               \
            r++;                                                          \
            if (r == 9) { r = 0; ci++; }                                  \
        }                                                                 \
    } while (0)

#define LOAD_A(t)                                                         \
    do {                                                                  \
        v0 = *(const float4*)(a_src + (t) * 16 + a_kq);                   \
        v1 = *(const float4*)(a_src + (t) * 16 + a_kq + 4);               \
    } while (0)

#define STORE_TILE(b)                                                     \
    do {                                                                  \
        *(u64*)&As2[b][a_kq + 0][2 * a_m] = dup2(v0.x);                   \
        *(u64*)&As2[b][a_kq + 1][2 * a_m] = dup2(v0.y);                   \
        *(u64*)&As2[b][a_kq + 2][2 * a_m] = dup2(v0.z);                   \
        *(u64*)&As2[b][a_kq + 3][2 * a_m] = dup2(v0.w);                   \
        *(u64*)&As2[b][a_kq + 4][2 * a_m] = dup2(v1.x);                   \
        *(u64*)&As2[b][a_kq + 5][2 * a_m] = dup2(v1.y);                   \
        *(u64*)&As2[b][a_kq + 6][2 * a_m] = dup2(v1.z);                   \
        *(u64*)&As2[b][a_kq + 7][2 * a_m] = dup2(v1.w);                   \
        _Pragma("unroll")                                                 \
        for (int q = 0; q < 16; q++) Bs[b][q][nnp] = bvals[q];            \
    } while (0)

    // prologue: tile 0 -> buf0, prefetch tile 1 into regs
    LOAD_A(0); GATHER_B();
    STORE_TILE(0);
    LOAD_A(1); GATHER_B();
    __syncthreads();

    for (int i = 0; i < NIT; i++) {
        const int buf = i & 1;
        // invariant: buf[i&1] holds tile i (synced); regs hold tile i+1
        if (i + 1 < NIT) STORE_TILE((i + 1) & 1);
        if (i + 2 < NIT) { LOAD_A(i + 2); GATHER_B(); }  // LDGs hide under compute

#pragma unroll
        for (int kk = 0; kk < 16; kk++) {
            ulonglong2 aA = *(const ulonglong2*)&As2[buf][kk][tmg * 16 + 0];
            ulonglong2 aB = *(const ulonglong2*)&As2[buf][kk][tmg * 16 + 4];
            ulonglong2 aC = *(const ulonglong2*)&As2[buf][kk][tmg * 16 + 8];
            ulonglong2 aD = *(const ulonglong2*)&As2[buf][kk][tmg * 16 + 12];
            ulonglong2 c0 = *(const ulonglong2*)&Bs[buf][kk][boff0];  // N 0-3
            ulonglong2 c1 = *(const ulonglong2*)&Bs[buf][kk][boff1];  // N 4-7
            u64 a2[8] = {aA.x, aA.y, aB.x, aB.y, aC.x, aC.y, aD.x, aD.y};
            u64 b2[4] = {c0.x, c0.y, c1.x, c1.y};
#pragma unroll
            for (int ii = 0; ii < 8; ii++)
#pragma unroll
                for (int p = 0; p < 4; p++)
                    acc[ii][p] = ffma2(a2[ii], b2[p], acc[ii][p]);
        }
        __syncthreads();   // compute(i) done; store(i+1) done -> next iter safe
    }

    // epilogue: store raw partial sums (bias+relu applied in head)
#pragma unroll
    for (int i = 0; i < 8; i++) {
        int co = co0 + tmg * 8 + i;
        float* dst = &gout[(size_t)co * HW + n0 + tng * 8];
#pragma unroll
        for (int p = 0; p < 4; p++) {
            float2 o;
            o.x = __uint_as_float((u32)(acc[i][p] & 0xFFFFFFFFull));
            o.y = __uint_as_float((u32)(acc[i][p] >> 32));
            *(float2*)(dst + 2 * p) = o;
        }
    }
#undef GATHER_B
#undef LOAD_A
#undef STORE_TILE
}

// =====================================================================
// Kernel 2: combine conv halves (+bias, relu) + 1x1 heads + softmax
// + anchor decode. (UNCHANGED from r13/r14)
// =====================================================================
__global__ void __launch_bounds__(256) head_kernel(
        const float* __restrict__ conv_b,
        const float* __restrict__ cls_w,  const float* __restrict__ cls_b,
        const float* __restrict__ bbox_w, const float* __restrict__ bbox_b,
        const float* __restrict__ im_info) {
    __shared__ float P[3][64][54];

    const int tid = threadIdx.x;
    const int nl  = tid & 63;
    const int half = tid >> 6;
    const int n = blockIdx.x * 64 + nl;
    const int cbase = half * 128;

    float acc[54];
#pragma unroll
    for (int j = 0; j < 54; j++) acc[j] = 0.f;

    for (int cb = 0; cb < 128; cb += 4) {
        int c = cbase + cb;
        float xv0 = fmaxf(g_xa[(size_t)(c + 0) * HW + n] + g_xb[(size_t)(c + 0) * HW + n] + conv_b[c + 0], 0.f);
        float xv1 = fmaxf(g_xa[(size_t)(c + 1) * HW + n] + g_xb[(size_t)(c + 1) * HW + n] + conv_b[c + 1], 0.f);
        float xv2 = fmaxf(g_xa[(size_t)(c + 2) * HW + n] + g_xb[(size_t)(c + 2) * HW + n] + conv_b[c + 2], 0.f);
        float xv3 = fmaxf(g_xa[(size_t)(c + 3) * HW + n] + g_xb[(size_t)(c + 3) * HW + n] + conv_b[c + 3], 0.f);
#pragma unroll
        for (int j = 0; j < 18; j++) {
            float4 wv = *(const float4*)(cls_w + j * CH + c);
            acc[j] += wv.x * xv0 + wv.y * xv1 + wv.z * xv2 + wv.w * xv3;
        }
#pragma unroll
        for (int j = 0; j < 36; j++) {
            float4 wv = *(const float4*)(bbox_w + j * CH + c);
            acc[18 + j] += wv.x * xv0 + wv.y * xv1 + wv.z * xv2 + wv.w * xv3;
        }
    }
    if (half > 0) {
#pragma unroll
        for (int j = 0; j < 54; j++) P[half - 1][nl][j] = acc[j];
    }
    __syncthreads();
    if (half != 0) return;

    float v[54];
#pragma unroll
    for (int j = 0; j < 54; j++) {
        float b = (j < 18) ? cls_b[j] : bbox_b[j - 18];
        v[j] = acc[j] + P[0][nl][j] + P[1][nl][j] + P[2][nl][j] + b;
    }

    const float im_h = im_info[0];
    const float im_w = im_info[1];
    const float ms   = 16.0f * im_info[2];
    const int  ph = n / FW;
    const int  pw = n - ph * FW;
    const float sx = (float)(pw * 16);
    const float sy = (float)(ph * 16);

#pragma unroll
    for (int a = 0; a < 9; a++) {
        float s0 = v[a], s1 = v[9 + a];
        float m  = fmaxf(s0, s1);
        float e0 = expf(s0 - m), e1 = expf(s1 - m);
        float score = e1 / (e0 + e1);

        float bx1 = c_anch[4 * a + 0] + sx;
        float by1 = c_anch[4 * a + 1] + sy;
        float bx2 = c_anch[4 * a + 2] + sx;
        float by2 = c_anch[4 * a + 3] + sy;
        float aw = bx2 - bx1 + 1.0f;
        float ah = by2 - by1 + 1.0f;
        float acx = bx1 + 0.5f * aw;
        float acy = by1 + 0.5f * ah;

        float d0 = v[18 + 4 * a + 0];
        float d1 = v[18 + 4 * a + 1];
        float d2 = v[18 + 4 * a + 2];
        float d3 = v[18 + 4 * a + 3];
        float cx = d0 * aw + acx;
        float cy = d1 * ah + acy;
        float pwid = expf(d2) * aw;
        float phei = expf(d3) * ah;

        float x1 = fminf(fmaxf(cx - 0.5f * pwid, 0.f), im_w - 1.0f);
        float y1 = fminf(fmaxf(cy - 0.5f * phei, 0.f), im_h - 1.0f);
        float x2 = fminf(fmaxf(cx + 0.5f * pwid, 0.f), im_w - 1.0f);
        float y2 = fminf(fmaxf(cy + 0.5f * phei, 0.f), im_h - 1.0f);

        bool keep = (x2 - x1 + 1.0f >= ms) && (y2 - y1 + 1.0f >= ms);
        float se = keep ? score : -__int_as_float(0x7F800000);  // -inf
        u32 sb = __float_as_uint(se);
        u32 mono = (sb & 0x80000000u) ? ~sb : (sb | 0x80000000u);
        int idx = n * 9 + a;
        g_keys[idx]  = ((u64)mono << 32) | (u64)(0xFFFFFFFFu - (u32)idx);
        g_boxes[idx] = make_float4(x1, y1, x2, y2);
    }
}

// ------------- pad keys [55296, 65536) with 0 (sorts last) -------------
// Idempotent; launched 3x so conv3 is launch #4 for ncu.
__global__ void pad_keys_kernel() {
    int i = blockIdx.x * blockDim.x + threadIdx.x;
    if (i < NSORT - NANCH) g_keys[NANCH + i] = 0ull;
}

// =====================================================================
// Bitonic top-k (UNCHANGED from r12-r14)
// =====================================================================
__device__ __forceinline__ void cswap(u64& a, u64& b, bool dec) {
    if (dec ? (a < b) : (a > b)) { u64 t = a; a = b; b = t; }
}

__global__ void __launch_bounds__(1024) sort4k_kernel() {
    __shared__ u64 S[4096];
    const int base = blockIdx.x * 4096;
    const int tid = threadIdx.x;
#pragma unroll
    for (int q = 0; q < 4; q++) S[tid + q * 1024] = g_keys[base + tid + q * 1024];
    __syncthreads();
    for (int k = 2; k <= 4096; k <<= 1) {
        for (int j = k >> 1; j > 0; j >>= 1) {
#pragma unroll
            for (int t0 = 0; t0 < 2; t0++) {
                int t = tid + t0 * 1024;
                int i = ((t & ~(j - 1)) << 1) | (t & (j - 1));
                bool dec = ((i & k) == 0);
                cswap(S[i], S[i + j], dec);
            }
            __syncthreads();
        }
    }
#pragma unroll
    for (int q = 0; q < 4; q++) g_keys[base + tid + q * 1024] = S[tid + q * 1024];
}

__global__ void __launch_bounds__(1024) fmerge8k_kernel() {
    extern __shared__ u64 S[];
    const int base = blockIdx.x * 8192;
    const int tid = threadIdx.x;
#pragma unroll
    for (int q = 0; q < 4; q++) {
        int i = tid + q * 1024;
        S[i]        = g_keys[base + i];
        S[4096 + i] = g_keys[base + 4096 + (4095 - i)];
    }
    __syncthreads();
    for (int j = 4096; j > 0; j >>= 1) {
#pragma unroll
        for (int t0 = 0; t0 < 4; t0++) {
            int t = tid + t0 * 1024;
            int i = ((t & ~(j - 1)) << 1) | (t & (j - 1));
            cswap(S[i], S[i + j], true);
        }
        __syncthreads();
    }
#pragma unroll
    for (int q = 0; q < 8; q++) g_keys[base + tid + q * 1024] = S[tid + q * 1024];
}

__global__ void __launch_bounds__(1024) prune8k_kernel(int stride) {
    extern __shared__ u64 S[];
    const int base1 = blockIdx.x * 2 * stride * 8192;
    const int base2 = base1 + stride * 8192;
    const int tid = threadIdx.x;
#pragma unroll
    for (int q = 0; q < 8; q++) {
        int i = tid + q * 1024;
        u64 a = g_keys[base1 + i];
        u64 b = g_keys[base2 + 8191 - i];
        S[i] = (a > b) ? a : b;
    }
    __syncthreads();
    for (int j = 4096; j > 0; j >>= 1) {
#pragma unroll
        for (int t0 = 0; t0 < 4; t0++) {
            int t = tid + t0 * 1024;
            int i = ((t & ~(j - 1)) << 1) | (t & (j - 1));
            cswap(S[i], S[i + j], true);
        }
        __syncthreads();
    }
#pragma unroll
    for (int q = 0; q < 8; q++) g_keys[base1 + tid + q * 1024] = S[tid + q * 1024];
}

// =====================================================================
// Greedy NMS v5: 192-word availability BITMASK.
//  - scanner warp covers 1024 slots per ballot step (<=6 steps)
//  - suppression: per-warp ballot, lane0 single word-AND (word
//    (s*32+warp) is owned exclusively by that warp -> no atomics)
//  - winner = lowest set bit; bits only ever clear -> monotone pointer
// =====================================================================
#define NMS_T 1024
#define NMS_S 6               // 1024*6 = 6144 slots >= 6000
#define NMS_N (NMS_T * NMS_S)
#define NMS_W (NMS_N / 32)    // 192 words

__global__ void __launch_bounds__(NMS_T) nms_kernel(float* __restrict__ out) {
    extern __shared__ char dsm[];
    float4* sbox = (float4*)dsm;                  // 6144*16 = 98304
    float*  sarea = (float*)(dsm + NMS_N * 16);   // 6144*4  = 24576

    __shared__ u32 avail[NMS_W];                  // bit=1: slot available
    __shared__ int s_win;
    __shared__ int s_wp;                          // word pointer (monotone)
    __shared__ float4 s_box;
    __shared__ float s_area;

    const int tid  = threadIdx.x;
    const int lane = tid & 31;
    const int wrp  = tid >> 5;

    float4 box[NMS_S];
    float  area[NMS_S];
    unsigned sup = 0;

#pragma unroll
    for (int s = 0; s < NMS_S; s++) {
        int p = s * NMS_T + tid;
        bool ok = false;
        float4 b = make_float4(0.f, 0.f, 0.f, 0.f);
        float A = 0.f;
        if (p < PRE_NMS) {
            u64 key = g_keys[p];
            u32 idx = 0xFFFFFFFFu - (u32)(key & 0xFFFFFFFFull);
            b = g_boxes[idx];
            A = (b.z - b.x + 1.0f) * (b.w - b.y + 1.0f);
            ok = ((u32)(key >> 32) > 0x007FFFFFu);
        }
        box[s] = b; area[s] = A;
        if (!ok) sup |= (1u << s);
        sbox[p] = b; sarea[p] = A;
        u32 bm = __ballot_sync(0xFFFFFFFFu, ok);
        if (lane == 0) avail[s * 32 + wrp] = bm;
    }
    if (tid == 0) s_wp = 0;
    __syncthreads();

    for (int it = 0; it < POST_NMS; it++) {
        // scanner warp: first set bit at/after word s_wp
        if (tid < 32) {
            int wp = s_wp;
            int found = -1, fw = -1;
            u32 word = 0;
            while (wp < NMS_W) {
                u32 v = (wp + tid < NMS_W) ? avail[wp + tid] : 0u;
                u32 m = __ballot_sync(0xFFFFFFFFu, v != 0u);
                if (m) {
                    int j = __ffs(m) - 1;
                    fw = wp + j;
                    word = __shfl_sync(0xFFFFFFFFu, v, j);
                    found = fw * 32 + (__ffs(word) - 1);
                    break;
                }
                wp += 32;
            }
            if (tid == 0) {
                s_win = found;
                if (found >= 0) {
                    s_wp = fw;
                    avail[fw] = word & (word - 1);   // clear winner bit
                    s_box = sbox[found];
                    s_area = sarea[found];
                } else {
                    s_wp = NMS_W;
                }
            }
        }
        __syncthreads();
        int win = s_win;

        if (tid == 0) {
            bool ok = (win >= 0);
            out[it * 5 + 0] = 0.f;
            out[it * 5 + 1] = ok ? s_box.x : 0.f;
            out[it * 5 + 2] = ok ? s_box.y : 0.f;
            out[it * 5 + 3] = ok ? s_box.z : 0.f;
            out[it * 5 + 4] = ok ? s_box.w : 0.f;
        }
        if (win >= 0) {
            float4 B = s_box;
            float A = s_area;
#pragma unroll
            for (int s = 0; s < NMS_S; s++) {
                bool newly = false;
                if (!(sup & (1u << s))) {
                    float xx1 = fmaxf(B.x, box[s].x);
                    float yy1 = fmaxf(B.y, box[s].y);
                    float xx2 = fminf(B.z, box[s].z);
                    float yy2 = fminf(B.w, box[s].w);
                    float inter = fmaxf(xx2 - xx1 + 1.0f, 0.f) *
                                  fmaxf(yy2 - yy1 + 1.0f, 0.f);
                    float iou = inter / (A + area[s] - inter);
                    if (iou > 0.7f) { newly = true; sup |= (1u << s); }
                }
                u32 m = __ballot_sync(0xFFFFFFFFu, newly);
                if (m && lane == 0) avail[s * 32 + wrp] &= ~m;
            }
        }
        __syncthreads();
    }
}

// =====================================================================
extern "C" void kernel_launch(void* const* d_in, const int* in_sizes, int n_in,
                              void* d_out, int out_size) {
    // Bind inputs by UNIQUE element count — robust to metadata ordering.
    const float *feat = 0, *im_info = 0, *conv_w = 0, *conv_b = 0;
    const float *cls_w = 0, *cls_b = 0, *bbox_w = 0, *bbox_b = 0;
    for (int i = 0; i < n_in; i++) {
        const float* p = (const float*)d_in[i];
        switch (in_sizes[i]) {
            case 3145728: feat    = p; break;
            case 3:       im_info = p; break;
            case 2359296: conv_w  = p; break;
            case 512:     conv_b  = p; break;
            case 9216:    cls_w   = p; break;
            case 18:      cls_b   = p; break;
            case 18432:   bbox_w  = p; break;
            case 36:      bbox_b  = p; break;
            default: break;
        }
    }
    if (!feat || !im_info || !conv_w || !conv_b || !cls_w || !cls_b || !bbox_w || !bbox_b) {
        feat    = (const float*)d_in[0];
        im_info = (const float*)d_in[1];
        conv_w  = (const float*)d_in[2];
        conv_b  = (const float*)d_in[3];
        cls_w   = (const float*)d_in[4];
        cls_b   = (const float*)d_in[5];
        bbox_w  = (const float*)d_in[6];
        bbox_b  = (const float*)d_in[7];
    }
    float* out = (float*)d_out;

    cudaFuncSetAttribute(fmerge8k_kernel,
                         cudaFuncAttributeMaxDynamicSharedMemorySize, 65536);
    cudaFuncSetAttribute(prune8k_kernel,
                         cudaFuncAttributeMaxDynamicSharedMemorySize, 65536);
    cudaFuncSetAttribute(nms_kernel,
                         cudaFuncAttributeMaxDynamicSharedMemorySize, NMS_N * 20);

    // pads first (independent, idempotent) so conv3 is launch #4 for ncu
    pad_keys_kernel<<<(NSORT - NANCH + 255) / 256, 256>>>();
    pad_keys_kernel<<<(NSORT - NANCH + 255) / 256, 256>>>();
    pad_keys_kernel<<<(NSORT - NANCH + 255) / 256, 256>>>();

    conv3_kernel<<<dim3(HW / 128, CH / 64, 2), 128>>>(feat, conv_w);
    head_kernel<<<HW / 64, 256>>>(conv_b, cls_w, cls_b, bbox_w, bbox_b, im_info);

    sort4k_kernel<<<16, 1024>>>();
    fmerge8k_kernel<<<8, 1024, 65536>>>();
    prune8k_kernel<<<4, 1024, 65536>>>(1);
    prune8k_kernel<<<2, 1024, 65536>>>(2);
    prune8k_kernel<<<1, 1024, 65536>>>(4);

    nms_kernel<<<1, NMS_T, NMS_N * 20>>>(out);
}

// round 16
// speedup vs baseline: 1.1687x; 1.1687x over previous
#include <cuda_runtime.h>
#include <cuda_bf16.h>
#include <cstdint>

#define CH    512
#define FH    64
#define FW    96
#define HW    6144          // 64*96
#define KDIM  4608          // 512*9
#define KHALF 2304          // 256 channels * 9
#define CHALF 256
#define NANCH 55296         // HW*9
#define NSORT 65536
#define PRE_NMS  6000
#define POST_NMS 300
#define NMS_N 6144          // padded candidate count
#define NMS_W (NMS_N / 32)  // 192 bitmap words

typedef unsigned long long u64;
typedef unsigned int u32;

// ------------- device scratch (no allocation allowed) -------------
__device__ float g_xa[CH * HW];       // conv partial, K-half 0 (raw)
__device__ float g_xb[CH * HW];       // conv partial, K-half 1
__device__ float4 g_boxes[NANCH];
__device__ u64   g_keys[NSORT];
__device__ float4 g_sbox[NMS_N];      // boxes in sorted order
__device__ float  g_sarea[NMS_N];
__device__ u32    g_avail[NMS_W];     // availability bitmap
__device__ u32    g_supp[NMS_N][NMS_W];  // suppression bitmatrix (4.7MB)

// base anchors, exact per reference _base_anchors() (verified passing r9)
__constant__ float c_anch[36] = {
    -84.f,  -40.f,  99.f,  55.f,
   -176.f,  -88.f, 191.f, 103.f,
   -360.f, -184.f, 375.f, 199.f,
    -56.f,  -56.f,  71.f,  71.f,
   -120.f, -120.f, 135.f, 135.f,
   -248.f, -248.f, 263.f, 263.f,
    -36.f,  -80.f,  51.f,  95.f,
    -80.f, -168.f,  95.f, 183.f,
   -168.f, -344.f, 183.f, 359.f
};

// ------------- packed fp32x2 helpers -------------
__device__ __forceinline__ u64 ffma2(u64 a, u64 b, u64 c) {
    u64 d;
    asm("fma.rn.f32x2 %0, %1, %2, %3;" : "=l"(d) : "l"(a), "l"(b), "l"(c));
    return d;
}
__device__ __forceinline__ u64 dup2(float v) {
    u32 u = __float_as_uint(v);
    return ((u64)u << 32) | (u64)u;
}

// =====================================================================
// Kernel 1: 3x3 conv — EXACT r14 version (measured 744us, best).
// Implicit GEMM, K split x2, tile 64Mx128N, BK=16, 128 thr, 8Mx8N FFMA2.
// A unduplicated in smem (reg-built pairs), B XOR-swizzled.
// =====================================================================
__global__ void __launch_bounds__(128) conv3_kernel(
        const float* __restrict__ feat,   // [512][64][96]
        const float* __restrict__ w) {    // [512][4608]
    __shared__ __align__(16) float As[16][64];    // [k][m] scalar
    __shared__ __align__(16) float Bs[16][128];   // [k][swizzled n]

    const int tid = threadIdx.x;
    const int n0  = blockIdx.x * 128;
    const int co0 = blockIdx.y * 64;
    const int half = blockIdx.z;          // 0 or 1
    const int kbase = half * KHALF;
    const int cibase = half * CHALF;
    float* gout = half ? g_xb : g_xa;

    const int tng = tid & 15;     // 16 N-groups of 8
    const int tmg = tid >> 4;     // 8  M-groups of 8
    const int sel = (tng >> 2) & 1;
    const int boff0 = tng * 8 + 4 * sel;
    const int boff1 = tng * 8 + 4 - 4 * sel;

    const int a_m  = tid >> 1;
    const int a_kq = (tid & 1) * 8;
    const float* a_src = w + (size_t)(co0 + a_m) * KDIM + kbase;

    const int nn   = tid;
    const int nnp  = nn ^ (((nn >> 5) & 1) << 2);
    const int n    = n0 + nn;
    const int ph   = n / FW;
    const int pw   = n - ph * FW;
    int ci = cibase, r = 0;

    u64 acc[8][4];
#pragma unroll
    for (int i = 0; i < 8; i++)
#pragma unroll
        for (int p = 0; p < 4; p++) acc[i][p] = 0ull;

    for (int k0 = 0; k0 < KHALF; k0 += 16) {
        float4 v0 = *(const float4*)(a_src + k0 + a_kq);
        float4 v1 = *(const float4*)(a_src + k0 + a_kq + 4);
        float bvals[16];
#pragma unroll
        for (int q = 0; q < 16; q++) {
            int rq = r;
            int dh = rq / 3 - 1;
            int dw = rq - (rq / 3) * 3 - 1;
            int hh = ph + dh, ww = pw + dw;
            float val = 0.f;
            if ((unsigned)hh < (unsigned)FH && (unsigned)ww < (unsigned)FW)
                val = feat[ci * HW + hh * FW + ww];
            bvals[q] = val;
            r++;
            if (r == 9) { r = 0; ci++; }
        }
        __syncthreads();
        As[a_kq + 0][a_m] = v0.x;
        As[a_kq + 1][a_m] = v0.y;
        As[a_kq + 2][a_m] = v0.z;
        As[a_kq + 3][a_m] = v0.w;
        As[a_kq + 4][a_m] = v1.x;
        As[a_kq + 5][a_m] = v1.y;
        As[a_kq + 6][a_m] = v1.z;
        As[a_kq + 7][a_m] = v1.w;
#pragma unroll
        for (int q = 0; q < 16; q++) Bs[q][nnp] = bvals[q];
        __syncthreads();

#pragma unroll
        for (int kk = 0; kk < 16; kk++) {
            float4 fa0 = *(const float4*)&As[kk][tmg * 8];
            float4 fa1 = *(const float4*)&As[kk][tmg * 8 + 4];
            ulonglong2 c0 = *(const ulonglong2*)&Bs[kk][boff0];
            ulonglong2 c1 = *(const ulonglong2*)&Bs[kk][boff1];
            u64 a2[8];
            a2[0] = dup2(fa0.x); a2[1] = dup2(fa0.y);
            a2[2] = dup2(fa0.z); a2[3] = dup2(fa0.w);
            a2[4] = dup2(fa1.x); a2[5] = dup2(fa1.y);
            a2[6] = dup2(fa1.z); a2[7] = dup2(fa1.w);
            u64 b2[4] = {c0.x, c0.y, c1.x, c1.y};
#pragma unroll
            for (int i = 0; i < 8; i++)
#pragma unroll
                for (int p = 0; p < 4; p++)
                    acc[i][p] = ffma2(a2[i], b2[p], acc[i][p]);
        }
    }

#pragma unroll
    for (int i = 0; i < 8; i++) {
        int co = co0 + tmg * 8 + i;
        float* dst = &gout[(size_t)co * HW + n0 + tng * 8];
#pragma unroll
        for (int p = 0; p < 4; p++) {
            float2 o;
            o.x = __uint_as_float((u32)(acc[i][p] & 0xFFFFFFFFull));
            o.y = __uint_as_float((u32)(acc[i][p] >> 32));
            *(float2*)(dst + 2 * p) = o;
        }
    }
}

// =====================================================================
// Kernel 2: combine conv halves (+bias, relu) + 1x1 heads + softmax
// + anchor decode. (UNCHANGED from r13/r14)
// =====================================================================
__global__ void __launch_bounds__(256) head_kernel(
        const float* __restrict__ conv_b,
        const float* __restrict__ cls_w,  const float* __restrict__ cls_b,
        const float* __restrict__ bbox_w, const float* __restrict__ bbox_b,
        const float* __restrict__ im_info) {
    __shared__ float P[3][64][54];

    const int tid = threadIdx.x;
    const int nl  = tid & 63;
    const int half = tid >> 6;
    const int n = blockIdx.x * 64 + nl;
    const int cbase = half * 128;

    float acc[54];
#pragma unroll
    for (int j = 0; j < 54; j++) acc[j] = 0.f;

    for (int cb = 0; cb < 128; cb += 4) {
        int c = cbase + cb;
        float xv0 = fmaxf(g_xa[(size_t)(c + 0) * HW + n] + g_xb[(size_t)(c + 0) * HW + n] + conv_b[c + 0], 0.f);
        float xv1 = fmaxf(g_xa[(size_t)(c + 1) * HW + n] + g_xb[(size_t)(c + 1) * HW + n] + conv_b[c + 1], 0.f);
        float xv2 = fmaxf(g_xa[(size_t)(c + 2) * HW + n] + g_xb[(size_t)(c + 2) * HW + n] + conv_b[c + 2], 0.f);
        float xv3 = fmaxf(g_xa[(size_t)(c + 3) * HW + n] + g_xb[(size_t)(c + 3) * HW + n] + conv_b[c + 3], 0.f);
#pragma unroll
        for (int j = 0; j < 18; j++) {
            float4 wv = *(const float4*)(cls_w + j * CH + c);
            acc[j] += wv.x * xv0 + wv.y * xv1 + wv.z * xv2 + wv.w * xv3;
        }
#pragma unroll
        for (int j = 0; j < 36; j++) {
            float4 wv = *(const float4*)(bbox_w + j * CH + c);
            acc[18 + j] += wv.x * xv0 + wv.y * xv1 + wv.z * xv2 + wv.w * xv3;
        }
    }
    if (half > 0) {
#pragma unroll
        for (int j = 0; j < 54; j++) P[half - 1][nl][j] = acc[j];
    }
    __syncthreads();
    if (half != 0) return;

    float v[54];
#pragma unroll
    for (int j = 0; j < 54; j++) {
        float b = (j < 18) ? cls_b[j] : bbox_b[j - 18];
        v[j] = acc[j] + P[0][nl][j] + P[1][nl][j] + P[2][nl][j] + b;
    }

    const float im_h = im_info[0];
    const float im_w = im_info[1];
    const float ms   = 16.0f * im_info[2];
    const int  ph = n / FW;
    const int  pw = n - ph * FW;
    const float sx = (float)(pw * 16);
    const float sy = (float)(ph * 16);

#pragma unroll
    for (int a = 0; a < 9; a++) {
        float s0 = v[a], s1 = v[9 + a];
        float m  = fmaxf(s0, s1);
        float e0 = expf(s0 - m), e1 = expf(s1 - m);
        float score = e1 / (e0 + e1);

        float bx1 = c_anch[4 * a + 0] + sx;
        float by1 = c_anch[4 * a + 1] + sy;
        float bx2 = c_anch[4 * a + 2] + sx;
        float by2 = c_anch[4 * a + 3] + sy;
        float aw = bx2 - bx1 + 1.0f;
        float ah = by2 - by1 + 1.0f;
        float acx = bx1 + 0.5f * aw;
        float acy = by1 + 0.5f * ah;

        float d0 = v[18 + 4 * a + 0];
        float d1 = v[18 + 4 * a + 1];
        float d2 = v[18 + 4 * a + 2];
        float d3 = v[18 + 4 * a + 3];
        float cx = d0 * aw + acx;
        float cy = d1 * ah + acy;
        float pwid = expf(d2) * aw;
        float phei = expf(d3) * ah;

        float x1 = fminf(fmaxf(cx - 0.5f * pwid, 0.f), im_w - 1.0f);
        float y1 = fminf(fmaxf(cy - 0.5f * phei, 0.f), im_h - 1.0f);
        float x2 = fminf(fmaxf(cx + 0.5f * pwid, 0.f), im_w - 1.0f);
        float y2 = fminf(fmaxf(cy + 0.5f * phei, 0.f), im_h - 1.0f);

        bool keep = (x2 - x1 + 1.0f >= ms) && (y2 - y1 + 1.0f >= ms);
        float se = keep ? score : -__int_as_float(0x7F800000);  // -inf
        u32 sb = __float_as_uint(se);
        u32 mono = (sb & 0x80000000u) ? ~sb : (sb | 0x80000000u);
        int idx = n * 9 + a;
        g_keys[idx]  = ((u64)mono << 32) | (u64)(0xFFFFFFFFu - (u32)idx);
        g_boxes[idx] = make_float4(x1, y1, x2, y2);
    }
}

// ------------- pad keys [55296, 65536) with 0 (sorts last) -------------
// Idempotent; launched 3x so conv3 is launch #4 for ncu.
__global__ void pad_keys_kernel() {
    int i = blockIdx.x * blockDim.x + threadIdx.x;
    if (i < NSORT - NANCH) g_keys[NANCH + i] = 0ull;
}

// =====================================================================
// Bitonic top-k (UNCHANGED from r12-r14)
// =====================================================================
__device__ __forceinline__ void cswap(u64& a, u64& b, bool dec) {
    if (dec ? (a < b) : (a > b)) { u64 t = a; a = b; b = t; }
}

__global__ void __launch_bounds__(1024) sort4k_kernel() {
    __shared__ u64 S[4096];
    const int base = blockIdx.x * 4096;
    const int tid = threadIdx.x;
#pragma unroll
    for (int q = 0; q < 4; q++) S[tid + q * 1024] = g_keys[base + tid + q * 1024];
    __syncthreads();
    for (int k = 2; k <= 4096; k <<= 1) {
        for (int j = k >> 1; j > 0; j >>= 1) {
#pragma unroll
            for (int t0 = 0; t0 < 2; t0++) {
                int t = tid + t0 * 1024;
                int i = ((t & ~(j - 1)) << 1) | (t & (j - 1));
                bool dec = ((i & k) == 0);
                cswap(S[i], S[i + j], dec);
            }
            __syncthreads();
        }
    }
#pragma unroll
    for (int q = 0; q < 4; q++) g_keys[base + tid + q * 1024] = S[tid + q * 1024];
}

__global__ void __launch_bounds__(1024) fmerge8k_kernel() {
    extern __shared__ u64 S[];
    const int base = blockIdx.x * 8192;
    const int tid = threadIdx.x;
#pragma unroll
    for (int q = 0; q < 4; q++) {
        int i = tid + q * 1024;
        S[i]        = g_keys[base + i];
        S[4096 + i] = g_keys[base + 4096 + (4095 - i)];
    }
    __syncthreads();
    for (int j = 4096; j > 0; j >>= 1) {
#pragma unroll
        for (int t0 = 0; t0 < 4; t0++) {
            int t = tid + t0 * 1024;
            int i = ((t & ~(j - 1)) << 1) | (t & (j - 1));
            cswap(S[i], S[i + j], true);
        }
        __syncthreads();
    }
#pragma unroll
    for (int q = 0; q < 8; q++) g_keys[base + tid + q * 1024] = S[tid + q * 1024];
}

__global__ void __launch_bounds__(1024) prune8k_kernel(int stride) {
    extern __shared__ u64 S[];
    const int base1 = blockIdx.x * 2 * stride * 8192;
    const int base2 = base1 + stride * 8192;
    const int tid = threadIdx.x;
#pragma unroll
    for (int q = 0; q < 8; q++) {
        int i = tid + q * 1024;
        u64 a = g_keys[base1 + i];
        u64 b = g_keys[base2 + 8191 - i];
        S[i] = (a > b) ? a : b;
    }
    __syncthreads();
    for (int j = 4096; j > 0; j >>= 1) {
#pragma unroll
        for (int t0 = 0; t0 < 4; t0++) {
            int t = tid + t0 * 1024;
            int i = ((t & ~(j - 1)) << 1) | (t & (j - 1));
            cswap(S[i], S[i + j], true);
        }
        __syncthreads();
    }
#pragma unroll
    for (int q = 0; q < 8; q++) g_keys[base1 + tid + q * 1024] = S[tid + q * 1024];
}

// =====================================================================
// NMS v6: parallel suppression matrix + single-warp resolve.
// Valid because a selected winner can only suppress LATER sorted
// positions (an earlier available box would have been argmax instead).
// =====================================================================

// prep: gather sorted boxes/areas, build availability bitmap
__global__ void __launch_bounds__(1024) nms_prep_kernel() {
    int p = blockIdx.x * 1024 + threadIdx.x;   // 6 blocks x 1024 = 6144
    bool ok = false;
    float4 b = make_float4(0.f, 0.f, 0.f, 0.f);
    float A = 0.f;
    if (p < PRE_NMS) {
        u64 key = g_keys[p];
        u32 idx = 0xFFFFFFFFu - (u32)(key & 0xFFFFFFFFull);
        b = g_boxes[idx];
        A = (b.z - b.x + 1.0f) * (b.w - b.y + 1.0f);
        ok = ((u32)(key >> 32) > 0x007FFFFFu);
    }
    g_sbox[p] = b;
    g_sarea[p] = A;
    u32 m = __ballot_sync(0xFFFFFFFFu, ok);
    if ((threadIdx.x & 31) == 0) g_avail[p >> 5] = m;
}

// matrix: g_supp[i] bit j (j>i) = IoU(box_i, box_j) > 0.7
// grid (24, 96): 256 cols x 64 rows per block; 2304 blocks.
__global__ void __launch_bounds__(256) nms_matrix_kernel() {
    __shared__ float4 rb[64];
    __shared__ float  ra[64];
    const int t   = threadIdx.x;
    const int r0  = blockIdx.y * 64;
    const int c0  = blockIdx.x * 256;
    if (t < 64) { rb[t] = g_sbox[r0 + t]; ra[t] = g_sarea[r0 + t]; }
    __syncthreads();

    const int j    = c0 + t;
    const float4 bj = g_sbox[j];
    const float  Aj = g_sarea[j];
    const int wid  = t >> 5;
    const int lane = t & 31;
    const int wcol = (c0 >> 5) + wid;

#pragma unroll 4
    for (int i0 = 0; i0 < 64; i0++) {
        const int i = r0 + i0;
        float4 bi = rb[i0];
        float  Ai = ra[i0];
        bool pred = false;
        if (j > i) {
            float xx1 = fmaxf(bi.x, bj.x);
            float yy1 = fmaxf(bi.y, bj.y);
            float xx2 = fminf(bi.z, bj.z);
            float yy2 = fminf(bi.w, bj.w);
            float inter = fmaxf(xx2 - xx1 + 1.0f, 0.f) *
                          fmaxf(yy2 - yy1 + 1.0f, 0.f);
            float iou = inter / ((Ai + Aj) - inter);
            pred = (iou > 0.7f);
        }
        u32 m = __ballot_sync(0xFFFFFFFFu, pred);
        if (lane == 0) g_supp[i][wcol] = m;
    }
}

// resolve: one warp, no block barriers. 300 selections.
__global__ void __launch_bounds__(32) nms_resolve_kernel(float* __restrict__ out) {
    __shared__ u32 avail[NMS_W];
    const int lane = threadIdx.x;
    for (int w2 = lane; w2 < NMS_W; w2 += 32) avail[w2] = g_avail[w2];
    __syncwarp();

    int wp = 0;   // monotone word pointer (all words before winner are 0)
    for (int it = 0; it < POST_NMS; it++) {
        int fw = -1; u32 word = 0;
        for (int b = wp; b < NMS_W; b += 32) {
            int idx = b + lane;
            u32 v = (idx < NMS_W) ? avail[idx] : 0u;
            u32 m = __ballot_sync(0xFFFFFFFFu, v != 0u);
            if (m) {
                int jj = __ffs(m) - 1;
                fw = b + jj;
                word = __shfl_sync(0xFFFFFFFFu, v, jj);
                break;
            }
        }
        int win = (fw >= 0) ? fw * 32 + (__ffs(word) - 1) : -1;

        float4 B = make_float4(0.f, 0.f, 0.f, 0.f);
        if (win >= 0) B = g_sbox[win];   // uniform load (broadcast)
        if (lane == 0) {
            out[it * 5 + 0] = 0.f;
            out[it * 5 + 1] = B.x;
            out[it * 5 + 2] = B.y;
            out[it * 5 + 3] = B.z;
            out[it * 5 + 4] = B.w;
        }
        if (win >= 0) {
            const u32* row = g_supp[win];
            u32 wbit = 1u << (win & 31);
            for (int w2 = lane; w2 < NMS_W; w2 += 32) {
                u32 clr = row[w2];
                if (w2 == fw) clr |= wbit;       // self-suppress, same owner lane
                avail[w2] &= ~clr;
            }
            wp = fw;
        }
        __syncwarp();
    }
}

// =====================================================================
extern "C" void kernel_launch(void* const* d_in, const int* in_sizes, int n_in,
                              void* d_out, int out_size) {
    // Bind inputs by UNIQUE element count — robust to metadata ordering.
    const float *feat = 0, *im_info = 0, *conv_w = 0, *conv_b = 0;
    const float *cls_w = 0, *cls_b = 0, *bbox_w = 0, *bbox_b = 0;
    for (int i = 0; i < n_in; i++) {
        const float* p = (const float*)d_in[i];
        switch (in_sizes[i]) {
            case 3145728: feat    = p; break;
            case 3:       im_info = p; break;
            case 2359296: conv_w  = p; break;
            case 512:     conv_b  = p; break;
            case 9216:    cls_w   = p; break;
            case 18:      cls_b   = p; break;
            case 18432:   bbox_w  = p; break;
            case 36:      bbox_b  = p; break;
            default: break;
        }
    }
    if (!feat || !im_info || !conv_w || !conv_b || !cls_w || !cls_b || !bbox_w || !bbox_b) {
        feat    = (const float*)d_in[0];
        im_info = (const float*)d_in[1];
        conv_w  = (const float*)d_in[2];
        conv_b  = (const float*)d_in[3];
        cls_w   = (const float*)d_in[4];
        cls_b   = (const float*)d_in[5];
        bbox_w  = (const float*)d_in[6];
        bbox_b  = (const float*)d_in[7];
    }
    float* out = (float*)d_out;

    cudaFuncSetAttribute(fmerge8k_kernel,
                         cudaFuncAttributeMaxDynamicSharedMemorySize, 65536);
    cudaFuncSetAttribute(prune8k_kernel,
                         cudaFuncAttributeMaxDynamicSharedMemorySize, 65536);

    // pads first (independent, idempotent) so conv3 is launch #4 for ncu
    pad_keys_kernel<<<(NSORT - NANCH + 255) / 256, 256>>>();
    pad_keys_kernel<<<(NSORT - NANCH + 255) / 256, 256>>>();
    pad_keys_kernel<<<(NSORT - NANCH + 255) / 256, 256>>>();

    conv3_kernel<<<dim3(HW / 128, CH / 64, 2), 128>>>(feat, conv_w);
    head_kernel<<<HW / 64, 256>>>(conv_b, cls_w, cls_b, bbox_w, bbox_b, im_info);

    sort4k_kernel<<<16, 1024>>>();
    fmerge8k_kernel<<<8, 1024, 65536>>>();
    prune8k_kernel<<<4, 1024, 65536>>>(1);
    prune8k_kernel<<<2, 1024, 65536>>>(2);
    prune8k_kernel<<<1, 1024, 65536>>>(4);

    nms_prep_kernel<<<NMS_N / 1024, 1024>>>();
    nms_matrix_kernel<<<dim3(NMS_N / 256, NMS_N / 64), 256>>>();
    nms_resolve_kernel<<<1, 32>>>(out);
}

// round 17
// speedup vs baseline: 1.2667x; 1.0839x over previous
#include <cuda_runtime.h>
#include <cuda_bf16.h>
#include <cstdint>

#define CH    512
#define FH    64
#define FW    96
#define HW    6144          // 64*96
#define PH2   66            // padded H
#define PW2   98            // padded W
#define PPLANE (PH2 * PW2)  // 6468
#define KDIM  4608          // 512*9
#define KHALF 2304          // 256 channels * 9
#define CHALF 256
#define NANCH 55296         // HW*9
#define NSORT 65536
#define PRE_NMS  6000
#define POST_NMS 300
#define NMS_N 6144          // padded candidate count
#define NMS_W (NMS_N / 32)  // 192 bitmap words

typedef unsigned long long u64;
typedef unsigned int u32;

// ------------- device scratch (no allocation allowed) -------------
__device__ float g_featp[CH * PPLANE];  // zero-padded feature map (13.2MB)
__device__ float g_xa[CH * HW];         // conv partial, K-half 0 (raw)
__device__ float g_xb[CH * HW];         // conv partial, K-half 1
__device__ float4 g_boxes[NANCH];
__device__ u64   g_keys[NSORT];
__device__ float4 g_sbox[NMS_N];        // boxes in sorted order
__device__ float  g_sarea[NMS_N];
__device__ u32    g_avail[NMS_W];       // availability bitmap
__device__ u32    g_supp[NMS_N][NMS_W]; // suppression bitmatrix (4.7MB)

// base anchors, exact per reference _base_anchors() (verified passing r9)
__constant__ float c_anch[36] = {
    -84.f,  -40.f,  99.f,  55.f,
   -176.f,  -88.f, 191.f, 103.f,
   -360.f, -184.f, 375.f, 199.f,
    -56.f,  -56.f,  71.f,  71.f,
   -120.f, -120.f, 135.f, 135.f,
   -248.f, -248.f, 263.f, 263.f,
    -36.f,  -80.f,  51.f,  95.f,
    -80.f, -168.f,  95.f, 183.f,
   -168.f, -344.f, 183.f, 359.f
};

// ------------- packed fp32x2 helpers -------------
__device__ __forceinline__ u64 ffma2(u64 a, u64 b, u64 c) {
    u64 d;
    asm("fma.rn.f32x2 %0, %1, %2, %3;" : "=l"(d) : "l"(a), "l"(b), "l"(c));
    return d;
}
__device__ __forceinline__ u64 dup2(float v) {
    u32 u = __float_as_uint(v);
    return ((u64)u << 32) | (u64)u;
}

// =====================================================================
// Kernel 0: stage feature map into zero-padded layout [512][66][98]
// + fold in the g_keys pad (indices NANCH..NSORT = 0).
// =====================================================================
__global__ void __launch_bounds__(256) padfeat_kernel(
        const float* __restrict__ feat) {
    int gid = blockIdx.x * 256 + threadIdx.x;
    if (gid < NSORT - NANCH) g_keys[NANCH + gid] = 0ull;
    if (gid >= CH * PPLANE) return;
    int c   = gid / PPLANE;
    int rem = gid - c * PPLANE;
    int hh  = rem / PW2;
    int ww  = rem - hh * PW2;
    int h = hh - 1, w2 = ww - 1;
    float v = 0.f;
    if ((unsigned)h < (unsigned)FH && (unsigned)w2 < (unsigned)FW)
        v = feat[c * HW + h * FW + w2];
    g_featp[gid] = v;
}

// =====================================================================
// Kernel 1: 3x3 conv — r14 structure (best measured), gather rewritten
// to read the PADDED feature map with an incremental pointer walk.
// Values bitwise identical (padded zeros == old masked zeros; same
// FFMA2 lane math in the same order). K split x2 via gridDim.z.
// =====================================================================
__global__ void __launch_bounds__(128) conv3_kernel(
        const float* __restrict__ w) {    // [512][4608]
    __shared__ __align__(16) float As[16][64];    // [k][m] scalar
    __shared__ __align__(16) float Bs[16][128];   // [k][swizzled n]

    const int tid = threadIdx.x;
    const int n0  = blockIdx.x * 128;
    const int co0 = blockIdx.y * 64;
    const int half = blockIdx.z;          // 0 or 1
    const int kbase = half * KHALF;
    const int cibase = half * CHALF;
    float* gout = half ? g_xb : g_xa;

    const int tng = tid & 15;     // 16 N-groups of 8
    const int tmg = tid >> 4;     // 8  M-groups of 8
    const int sel = (tng >> 2) & 1;
    const int boff0 = tng * 8 + 4 * sel;
    const int boff1 = tng * 8 + 4 - 4 * sel;

    const int a_m  = tid >> 1;
    const int a_kq = (tid & 1) * 8;
    const float* a_src = w + (size_t)(co0 + a_m) * KDIM + kbase;

    const int nn   = tid;
    const int nnp  = nn ^ (((nn >> 5) & 1) << 2);
    const int n    = n0 + nn;
    const int ph   = n / FW;
    const int pw   = n - ph * FW;

    // incremental im2col pointer into padded map:
    // position (ci, r): padded addr = ci*6468 + (ph+dh(r))*98 + pw+dw(r)+... 
    // r=0 (dh=-1,dw=-1) -> ci*6468 + ph*98 + pw.
    // per-step deltas: {1,1,96,1,1,96,1,1,6270} realized as
    // +1 each step; on c3 wrap +95; on c9 wrap +6174.
    int addr = cibase * PPLANE + ph * PW2 + pw;
    int c3 = 0, c9 = 0;

    u64 acc[8][4];
#pragma unroll
    for (int i = 0; i < 8; i++)
#pragma unroll
        for (int p = 0; p < 4; p++) acc[i][p] = 0ull;

    for (int k0 = 0; k0 < KHALF; k0 += 16) {
        float4 v0 = *(const float4*)(a_src + k0 + a_kq);
        float4 v1 = *(const float4*)(a_src + k0 + a_kq + 4);
        float bvals[16];
#pragma unroll
        for (int q = 0; q < 16; q++) {
            bvals[q] = g_featp[addr];
            addr += 1;
            if (++c3 == 3) {
                c3 = 0; addr += 95;
                if (++c9 == 3) { c9 = 0; addr += 6174; }
            }
        }
        __syncthreads();
        As[a_kq + 0][a_m] = v0.x;
        As[a_kq + 1][a_m] = v0.y;
        As[a_kq + 2][a_m] = v0.z;
        As[a_kq + 3][a_m] = v0.w;
        As[a_kq + 4][a_m] = v1.x;
        As[a_kq + 5][a_m] = v1.y;
        As[a_kq + 6][a_m] = v1.z;
        As[a_kq + 7][a_m] = v1.w;
#pragma unroll
        for (int q = 0; q < 16; q++) Bs[q][nnp] = bvals[q];
        __syncthreads();

#pragma unroll
        for (int kk = 0; kk < 16; kk++) {
            float4 fa0 = *(const float4*)&As[kk][tmg * 8];
            float4 fa1 = *(const float4*)&As[kk][tmg * 8 + 4];
            ulonglong2 c0 = *(const ulonglong2*)&Bs[kk][boff0];
            ulonglong2 c1 = *(const ulonglong2*)&Bs[kk][boff1];
            u64 a2[8];
            a2[0] = dup2(fa0.x); a2[1] = dup2(fa0.y);
            a2[2] = dup2(fa0.z); a2[3] = dup2(fa0.w);
            a2[4] = dup2(fa1.x); a2[5] = dup2(fa1.y);
            a2[6] = dup2(fa1.z); a2[7] = dup2(fa1.w);
            u64 b2[4] = {c0.x, c0.y, c1.x, c1.y};
#pragma unroll
            for (int i = 0; i < 8; i++)
#pragma unroll
                for (int p = 0; p < 4; p++)
                    acc[i][p] = ffma2(a2[i], b2[p], acc[i][p]);
        }
    }

#pragma unroll
    for (int i = 0; i < 8; i++) {
        int co = co0 + tmg * 8 + i;
        float* dst = &gout[(size_t)co * HW + n0 + tng * 8];
#pragma unroll
        for (int p = 0; p < 4; p++) {
            float2 o;
            o.x = __uint_as_float((u32)(acc[i][p] & 0xFFFFFFFFull));
            o.y = __uint_as_float((u32)(acc[i][p] >> 32));
            *(float2*)(dst + 2 * p) = o;
        }
    }
}

// =====================================================================
// Kernel 2: combine conv halves (+bias, relu) + 1x1 heads + softmax
// + anchor decode. (UNCHANGED from r13-r16)
// =====================================================================
__global__ void __launch_bounds__(256) head_kernel(
        const float* __restrict__ conv_b,
        const float* __restrict__ cls_w,  const float* __restrict__ cls_b,
        const float* __restrict__ bbox_w, const float* __restrict__ bbox_b,
        const float* __restrict__ im_info) {
    __shared__ float P[3][64][54];

    const int tid = threadIdx.x;
    const int nl  = tid & 63;
    const int half = tid >> 6;
    const int n = blockIdx.x * 64 + nl;
    const int cbase = half * 128;

    float acc[54];
#pragma unroll
    for (int j = 0; j < 54; j++) acc[j] = 0.f;

    for (int cb = 0; cb < 128; cb += 4) {
        int c = cbase + cb;
        float xv0 = fmaxf(g_xa[(size_t)(c + 0) * HW + n] + g_xb[(size_t)(c + 0) * HW + n] + conv_b[c + 0], 0.f);
        float xv1 = fmaxf(g_xa[(size_t)(c + 1) * HW + n] + g_xb[(size_t)(c + 1) * HW + n] + conv_b[c + 1], 0.f);
        float xv2 = fmaxf(g_xa[(size_t)(c + 2) * HW + n] + g_xb[(size_t)(c + 2) * HW + n] + conv_b[c + 2], 0.f);
        float xv3 = fmaxf(g_xa[(size_t)(c + 3) * HW + n] + g_xb[(size_t)(c + 3) * HW + n] + conv_b[c + 3], 0.f);
#pragma unroll
        for (int j = 0; j < 18; j++) {
            float4 wv = *(const float4*)(cls_w + j * CH + c);
            acc[j] += wv.x * xv0 + wv.y * xv1 + wv.z * xv2 + wv.w * xv3;
        }
#pragma unroll
        for (int j = 0; j < 36; j++) {
            float4 wv = *(const float4*)(bbox_w + j * CH + c);
            acc[18 + j] += wv.x * xv0 + wv.y * xv1 + wv.z * xv2 + wv.w * xv3;
        }
    }
    if (half > 0) {
#pragma unroll
        for (int j = 0; j < 54; j++) P[half - 1][nl][j] = acc[j];
    }
    __syncthreads();
    if (half != 0) return;

    float v[54];
#pragma unroll
    for (int j = 0; j < 54; j++) {
        float b = (j < 18) ? cls_b[j] : bbox_b[j - 18];
        v[j] = acc[j] + P[0][nl][j] + P[1][nl][j] + P[2][nl][j] + b;
    }

    const float im_h = im_info[0];
    const float im_w = im_info[1];
    const float ms   = 16.0f * im_info[2];
    const int  ph = n / FW;
    const int  pw = n - ph * FW;
    const float sx = (float)(pw * 16);
    const float sy = (float)(ph * 16);

#pragma unroll
    for (int a = 0; a < 9; a++) {
        float s0 = v[a], s1 = v[9 + a];
        float m  = fmaxf(s0, s1);
        float e0 = expf(s0 - m), e1 = expf(s1 - m);
        float score = e1 / (e0 + e1);

        float bx1 = c_anch[4 * a + 0] + sx;
        float by1 = c_anch[4 * a + 1] + sy;
        float bx2 = c_anch[4 * a + 2] + sx;
        float by2 = c_anch[4 * a + 3] + sy;
        float aw = bx2 - bx1 + 1.0f;
        float ah = by2 - by1 + 1.0f;
        float acx = bx1 + 0.5f * aw;
        float acy = by1 + 0.5f * ah;

        float d0 = v[18 + 4 * a + 0];
        float d1 = v[18 + 4 * a + 1];
        float d2 = v[18 + 4 * a + 2];
        float d3 = v[18 + 4 * a + 3];
        float cx = d0 * aw + acx;
        float cy = d1 * ah + acy;
        float pwid = expf(d2) * aw;
        float phei = expf(d3) * ah;

        float x1 = fminf(fmaxf(cx - 0.5f * pwid, 0.f), im_w - 1.0f);
        float y1 = fminf(fmaxf(cy - 0.5f * phei, 0.f), im_h - 1.0f);
        float x2 = fminf(fmaxf(cx + 0.5f * pwid, 0.f), im_w - 1.0f);
        float y2 = fminf(fmaxf(cy + 0.5f * phei, 0.f), im_h - 1.0f);

        bool keep = (x2 - x1 + 1.0f >= ms) && (y2 - y1 + 1.0f >= ms);
        float se = keep ? score : -__int_as_float(0x7F800000);  // -inf
        u32 sb = __float_as_uint(se);
        u32 mono = (sb & 0x80000000u) ? ~sb : (sb | 0x80000000u);
        int idx = n * 9 + a;
        g_keys[idx]  = ((u64)mono << 32) | (u64)(0xFFFFFFFFu - (u32)idx);
        g_boxes[idx] = make_float4(x1, y1, x2, y2);
    }
}

// =====================================================================
// Bitonic top-k (UNCHANGED from r12-r16)
// =====================================================================
__device__ __forceinline__ void cswap(u64& a, u64& b, bool dec) {
    if (dec ? (a < b) : (a > b)) { u64 t = a; a = b; b = t; }
}

__global__ void __launch_bounds__(1024) sort4k_kernel() {
    __shared__ u64 S[4096];
    const int base = blockIdx.x * 4096;
    const int tid = threadIdx.x;
#pragma unroll
    for (int q = 0; q < 4; q++) S[tid + q * 1024] = g_keys[base + tid + q * 1024];
    __syncthreads();
    for (int k = 2; k <= 4096; k <<= 1) {
        for (int j = k >> 1; j > 0; j >>= 1) {
#pragma unroll
            for (int t0 = 0; t0 < 2; t0++) {
                int t = tid + t0 * 1024;
                int i = ((t & ~(j - 1)) << 1) | (t & (j - 1));
                bool dec = ((i & k) == 0);
                cswap(S[i], S[i + j], dec);
            }
            __syncthreads();
        }
    }
#pragma unroll
    for (int q = 0; q < 4; q++) g_keys[base + tid + q * 1024] = S[tid + q * 1024];
}

__global__ void __launch_bounds__(1024) fmerge8k_kernel() {
    extern __shared__ u64 S[];
    const int base = blockIdx.x * 8192;
    const int tid = threadIdx.x;
#pragma unroll
    for (int q = 0; q < 4; q++) {
        int i = tid + q * 1024;
        S[i]        = g_keys[base + i];
        S[4096 + i] = g_keys[base + 4096 + (4095 - i)];
    }
    __syncthreads();
    for (int j = 4096; j > 0; j >>= 1) {
#pragma unroll
        for (int t0 = 0; t0 < 4; t0++) {
            int t = tid + t0 * 1024;
            int i = ((t & ~(j - 1)) << 1) | (t & (j - 1));
            cswap(S[i], S[i + j], true);
        }
        __syncthreads();
    }
#pragma unroll
    for (int q = 0; q < 8; q++) g_keys[base + tid + q * 1024] = S[tid + q * 1024];
}

__global__ void __launch_bounds__(1024) prune8k_kernel(int stride) {
    extern __shared__ u64 S[];
    const int base1 = blockIdx.x * 2 * stride * 8192;
    const int base2 = base1 + stride * 8192;
    const int tid = threadIdx.x;
#pragma unroll
    for (int q = 0; q < 8; q++) {
        int i = tid + q * 1024;
        u64 a = g_keys[base1 + i];
        u64 b = g_keys[base2 + 8191 - i];
        S[i] = (a > b) ? a : b;
    }
    __syncthreads();
    for (int j = 4096; j > 0; j >>= 1) {
#pragma unroll
        for (int t0 = 0; t0 < 4; t0++) {
            int t = tid + t0 * 1024;
            int i = ((t & ~(j - 1)) << 1) | (t & (j - 1));
            cswap(S[i], S[i + j], true);
        }
        __syncthreads();
    }
#pragma unroll
    for (int q = 0; q < 8; q++) g_keys[base1 + tid + q * 1024] = S[tid + q * 1024];
}

// =====================================================================
// NMS: parallel suppression matrix + single-warp resolve (r16 WIN),
// r17: resolve stages all boxes in 98KB smem (winner fetch ~LDS).
// =====================================================================
__global__ void __launch_bounds__(1024) nms_prep_kernel() {
    int p = blockIdx.x * 1024 + threadIdx.x;
    bool ok = false;
    float4 b = make_float4(0.f, 0.f, 0.f, 0.f);
    float A = 0.f;
    if (p < PRE_NMS) {
        u64 key = g_keys[p];
        u32 idx = 0xFFFFFFFFu - (u32)(key & 0xFFFFFFFFull);
        b = g_boxes[idx];
        A = (b.z - b.x + 1.0f) * (b.w - b.y + 1.0f);
        ok = ((u32)(key >> 32) > 0x007FFFFFu);
    }
    g_sbox[p] = b;
    g_sarea[p] = A;
    u32 m = __ballot_sync(0xFFFFFFFFu, ok);
    if ((threadIdx.x & 31) == 0) g_avail[p >> 5] = m;
}

__global__ void __launch_bounds__(256) nms_matrix_kernel() {
    __shared__ float4 rb[64];
    __shared__ float  ra[64];
    const int t   = threadIdx.x;
    const int r0  = blockIdx.y * 64;
    const int c0  = blockIdx.x * 256;
    if (t < 64) { rb[t] = g_sbox[r0 + t]; ra[t] = g_sarea[r0 + t]; }
    __syncthreads();

    const int j    = c0 + t;
    const float4 bj = g_sbox[j];
    const float  Aj = g_sarea[j];
    const int wid  = t >> 5;
    const int lane = t & 31;
    const int wcol = (c0 >> 5) + wid;

#pragma unroll 4
    for (int i0 = 0; i0 < 64; i0++) {
        const int i = r0 + i0;
        float4 bi = rb[i0];
        float  Ai = ra[i0];
        bool pred = false;
        if (j > i) {
            float xx1 = fmaxf(bi.x, bj.x);
            float yy1 = fmaxf(bi.y, bj.y);
            float xx2 = fminf(bi.z, bj.z);
            float yy2 = fminf(bi.w, bj.w);
            float inter = fmaxf(xx2 - xx1 + 1.0f, 0.f) *
                          fmaxf(yy2 - yy1 + 1.0f, 0.f);
            float iou = inter / ((Ai + Aj) - inter);
            pred = (iou > 0.7f);
        }
        u32 m = __ballot_sync(0xFFFFFFFFu, pred);
        if (lane == 0) g_supp[i][wcol] = m;
    }
}

__global__ void __launch_bounds__(32) nms_resolve_kernel(float* __restrict__ out) {
    extern __shared__ float4 sb[];                // 6144 boxes = 98304 B
    __shared__ u32 avail[NMS_W];
    const int lane = threadIdx.x;
    for (int i = lane; i < NMS_N; i += 32) sb[i] = g_sbox[i];
    for (int w2 = lane; w2 < NMS_W; w2 += 32) avail[w2] = g_avail[w2];
    __syncwarp();

    int wp = 0;
    for (int it = 0; it < POST_NMS; it++) {
        int fw = -1; u32 word = 0;
        for (int b = wp; b < NMS_W; b += 32) {
            int idx = b + lane;
            u32 v = (idx < NMS_W) ? avail[idx] : 0u;
            u32 m = __ballot_sync(0xFFFFFFFFu, v != 0u);
            if (m) {
                int jj = __ffs(m) - 1;
                fw = b + jj;
                word = __shfl_sync(0xFFFFFFFFu, v, jj);
                break;
            }
        }
        int win = (fw >= 0) ? fw * 32 + (__ffs(word) - 1) : -1;

        float4 B = make_float4(0.f, 0.f, 0.f, 0.f);
        if (win >= 0) B = sb[win];
        if (lane == 0) {
            out[it * 5 + 0] = 0.f;
            out[it * 5 + 1] = B.x;
            out[it * 5 + 2] = B.y;
            out[it * 5 + 3] = B.z;
            out[it * 5 + 4] = B.w;
        }
        if (win >= 0) {
            const u32* row = g_supp[win];
            u32 wbit = 1u << (win & 31);
            for (int w2 = lane; w2 < NMS_W; w2 += 32) {
                u32 clr = row[w2];
                if (w2 == fw) clr |= wbit;
                avail[w2] &= ~clr;
            }
            wp = fw;
        }
        __syncwarp();
    }
}

// =====================================================================
extern "C" void kernel_launch(void* const* d_in, const int* in_sizes, int n_in,
                              void* d_out, int out_size) {
    const float *feat = 0, *im_info = 0, *conv_w = 0, *conv_b = 0;
    const float *cls_w = 0, *cls_b = 0, *bbox_w = 0, *bbox_b = 0;
    for (int i = 0; i < n_in; i++) {
        const float* p = (const float*)d_in[i];
        switch (in_sizes[i]) {
            case 3145728: feat    = p; break;
            case 3:       im_info = p; break;
            case 2359296: conv_w  = p; break;
            case 512:     conv_b  = p; break;
            case 9216:    cls_w   = p; break;
            case 18:      cls_b   = p; break;
            case 18432:   bbox_w  = p; break;
            case 36:      bbox_b  = p; break;
            default: break;
        }
    }
    if (!feat || !im_info || !conv_w || !conv_b || !cls_w || !cls_b || !bbox_w || !bbox_b) {
        feat    = (const float*)d_in[0];
        im_info = (const float*)d_in[1];
        conv_w  = (const float*)d_in[2];
        conv_b  = (const float*)d_in[3];
        cls_w   = (const float*)d_in[4];
        cls_b   = (const float*)d_in[5];
        bbox_w  = (const float*)d_in[6];
        bbox_b  = (const float*)d_in[7];
    }
    float* out = (float*)d_out;

    cudaFuncSetAttribute(fmerge8k_kernel,
                         cudaFuncAttributeMaxDynamicSharedMemorySize, 65536);
    cudaFuncSetAttribute(prune8k_kernel,
                         cudaFuncAttributeMaxDynamicSharedMemorySize, 65536);
    cudaFuncSetAttribute(nms_resolve_kernel,
                         cudaFuncAttributeMaxDynamicSharedMemorySize, NMS_N * 16);

    // launch order: padfeat(1) conv(2) head(3) sort4k(4 <- ncu probe) ...
    padfeat_kernel<<<(CH * PPLANE + 255) / 256, 256>>>(feat);
    conv3_kernel<<<dim3(HW / 128, CH / 64, 2), 128>>>(conv_w);
    head_kernel<<<HW / 64, 256>>>(conv_b, cls_w, cls_b, bbox_w, bbox_b, im_info);

    sort4k_kernel<<<16, 1024>>>();
    fmerge8k_kernel<<<8, 1024, 65536>>>();
    prune8k_kernel<<<4, 1024, 65536>>>(1);
    prune8k_kernel<<<2, 1024, 65536>>>(2);
    prune8k_kernel<<<1, 1024, 65536>>>(4);

    nms_prep_kernel<<<NMS_N / 1024, 1024>>>();
    nms_matrix_kernel<<<dim3(NMS_N / 256, NMS_N / 64), 256>>>();
    nms_resolve_kernel<<<1, 32, NMS_N * 16>>>(out);
}